// round 1
// baseline (speedup 1.0000x reference)
#include <cuda_runtime.h>

#define BATCH    4096
#define IN_FEAT  4096
#define NSITES   512
#define NPAIRS_TOTAL 767   // 256 + 255 + 256

typedef unsigned long long ull;

// ---------------- scratch (device globals; no allocation allowed) ----------------
__device__ float g_h[(size_t)BATCH * IN_FEAT];        // 64 MB intermediate h
__device__ float g_gred[(size_t)NPAIRS_TOTAL * 1024]; // per (layer,pair): G1[512] | G2[512]

// ---------------- packed f32x2 helpers (Blackwell) ----------------
__device__ __forceinline__ ull pack2(float c) {
    ull r; asm("mov.b64 %0, {%1, %1};" : "=l"(r) : "f"(c)); return r;
}
__device__ __forceinline__ void fma2(ull& d, ull a, ull b) {
    asm("fma.rn.f32x2 %0, %1, %2, %3;" : "=l"(d) : "l"(a), "l"(b), "l"(d));
}
__device__ __forceinline__ float2 unpack2(ull v) {
    float2 f; asm("mov.b64 {%0, %1}, %2;" : "=f"(f.x), "=f"(f.y) : "l"(v)); return f;
}

// ---------------- Kernel A: gate reduction ----------------
// For each global pair gb (layer-concatenated):
//   G[i,j,m,n]   = sum_{r1,r2} gates[k,r1,r2,i,j,m,n]
//   G1[i,j,m]    = sum_n G       -> g_gred[gb][ (i*8+j)*8+m ]
//   G2[i,j,n]    = sum_m G       -> g_gred[gb][ 512 + (i*8+j)*8+n ]
__global__ __launch_bounds__(256) void reduce_gates_kernel(
    const float* __restrict__ g0, const float* __restrict__ g1, const float* __restrict__ g2)
{
    __shared__ float sG[4096];
    int gb = blockIdx.x;
    const float* src;
    if (gb < 256)      src = g0 + (size_t)gb * 65536;          // 16*4096 per pair
    else if (gb < 511) src = g1 + (size_t)(gb - 256) * 65536;
    else               src = g2 + (size_t)(gb - 511) * 65536;

    int tid = threadIdx.x;
    float acc[16];
#pragma unroll
    for (int t = 0; t < 16; t++) acc[t] = 0.f;
#pragma unroll
    for (int rc = 0; rc < 16; rc++) {
        const float* p = src + rc * 4096;
#pragma unroll
        for (int t = 0; t < 16; t++) acc[t] += p[t * 256 + tid];
    }
#pragma unroll
    for (int t = 0; t < 16; t++) sG[t * 256 + tid] = acc[t];
    __syncthreads();

    float* dst = g_gred + (size_t)gb * 1024;
#pragma unroll
    for (int u = 0; u < 2; u++) {
        int o = u * 256 + tid;          // 0..511
        float s1 = 0.f;
#pragma unroll
        for (int n = 0; n < 8; n++) s1 += sG[o * 8 + n];
        dst[o] = s1;
        int ij = o >> 3, nn = o & 7;
        float s2 = 0.f;
#pragma unroll
        for (int m = 0; m < 8; m++) s2 += sG[ij * 64 + m * 8 + nn];
        dst[512 + o] = s2;
    }
}

// ---------------- Kernel B: permuted gather  h[b,q] = x[b, perm[q]] ----------------
// One block per batch row: the row (16KB) stays resident in L1, so the random
// in-row 4B reads re-use every 32B sector fully. Writes are coalesced.
__global__ __launch_bounds__(256) void gather_kernel(
    const float* __restrict__ x, const int* __restrict__ perm)
{
    int b = blockIdx.x;
    const float* xr = x + (size_t)b * IN_FEAT;
    float* hr = g_h + (size_t)b * IN_FEAT;
    int tid = threadIdx.x;
#pragma unroll
    for (int c = 0; c < 16; c++) {
        int q = c * 256 + tid;
        hr[q] = xr[perm[q]];
    }
}

// ---------------- Layer kernel ----------------
// grid = (P, 8). Block: 256 threads, each handles rows (by*512 + tid) and (+256)
// for one pair k (sites OFFSET+2k, OFFSET+2k+1). Gates staged in SMEM (4KB),
// read warp-uniform (broadcast). In-place update; EPI fuses the final epilogue.
template<int OFFSET, bool EPI>
__global__ __launch_bounds__(256) void layer_kernel(
    int gate_base,
    const float* __restrict__ alphap,
    const float* __restrict__ scale,
    const float* __restrict__ bias,
    float* __restrict__ out)
{
    __shared__ float sg[1024];
    int k = blockIdx.x;
    ((float4*)sg)[threadIdx.x] =
        ((const float4*)(g_gred + ((size_t)(gate_base + k)) * 1024))[threadIdx.x];
    __syncthreads();

    const size_t col = ((size_t)(OFFSET + 2 * k)) * 8;   // first of 16 contiguous floats
    const int r0 = blockIdx.y * 512 + threadIdx.x;

    float x1[2][8], x2[2][8];
#pragma unroll
    for (int rr = 0; rr < 2; rr++) {
        const float4* hp = (const float4*)(g_h + (size_t)(r0 + rr * 256) * IN_FEAT + col);
        float4 a0 = hp[0], a1 = hp[1], b0 = hp[2], b1 = hp[3];
        x1[rr][0]=a0.x; x1[rr][1]=a0.y; x1[rr][2]=a0.z; x1[rr][3]=a0.w;
        x1[rr][4]=a1.x; x1[rr][5]=a1.y; x1[rr][6]=a1.z; x1[rr][7]=a1.w;
        x2[rr][0]=b0.x; x2[rr][1]=b0.y; x2[rr][2]=b0.z; x2[rr][3]=b0.w;
        x2[rr][4]=b1.x; x2[rr][5]=b1.y; x2[rr][6]=b1.z; x2[rr][7]=b1.w;
    }

    ull acc1[2][4], acc2[2][4];
#pragma unroll
    for (int rr = 0; rr < 2; rr++)
#pragma unroll
        for (int t = 0; t < 4; t++) { acc1[rr][t] = 0ull; acc2[rr][t] = 0ull; }

    const ulonglong2* sgv = (const ulonglong2*)sg;   // 16B = 2 packed f32x2
#pragma unroll
    for (int i = 0; i < 8; i++) {
#pragma unroll
        for (int j = 0; j < 8; j++) {
            int ij = i * 8 + j;
            ulonglong2 p = sgv[ij * 2];          // G1[ij][0..3]
            ulonglong2 q = sgv[ij * 2 + 1];      // G1[ij][4..7]
            ulonglong2 r = sgv[128 + ij * 2];    // G2[ij][0..3]  (512 floats offset)
            ulonglong2 s = sgv[128 + ij * 2 + 1];// G2[ij][4..7]
#pragma unroll
            for (int rr = 0; rr < 2; rr++) {
                ull cd = pack2(x1[rr][i] * x2[rr][j]);
                fma2(acc1[rr][0], cd, p.x); fma2(acc1[rr][1], cd, p.y);
                fma2(acc1[rr][2], cd, q.x); fma2(acc1[rr][3], cd, q.y);
                fma2(acc2[rr][0], cd, r.x); fma2(acc2[rr][1], cd, r.y);
                fma2(acc2[rr][2], cd, s.x); fma2(acc2[rr][3], cd, s.y);
            }
        }
    }

    float al = 1.f;
    float sc[16], bi[16];
    if (EPI) {
        al = __ldg(alphap);
#pragma unroll
        for (int t = 0; t < 16; t++) { sc[t] = __ldg(scale + col + t); bi[t] = __ldg(bias + col + t); }
    }

#pragma unroll
    for (int rr = 0; rr < 2; rr++) {
        float y[16];
#pragma unroll
        for (int t = 0; t < 4; t++) {
            float2 f1 = unpack2(acc1[rr][t]); y[2 * t]     = f1.x; y[2 * t + 1]     = f1.y;
            float2 f2 = unpack2(acc2[rr][t]); y[8 + 2 * t] = f2.x; y[8 + 2 * t + 1] = f2.y;
        }
        size_t base = (size_t)(r0 + rr * 256) * IN_FEAT + col;
        if (!EPI) {
            float4* hp = (float4*)(g_h + base);
            hp[0] = make_float4(y[0], y[1], y[2], y[3]);
            hp[1] = make_float4(y[4], y[5], y[6], y[7]);
            hp[2] = make_float4(y[8], y[9], y[10], y[11]);
            hp[3] = make_float4(y[12], y[13], y[14], y[15]);
        } else {
#pragma unroll
            for (int t = 0; t < 16; t++) y[t] = al * y[t] * sc[t] + bi[t];
            float4* op = (float4*)(out + base);
            op[0] = make_float4(y[0], y[1], y[2], y[3]);
            op[1] = make_float4(y[4], y[5], y[6], y[7]);
            op[2] = make_float4(y[8], y[9], y[10], y[11]);
            op[3] = make_float4(y[12], y[13], y[14], y[15]);
        }
    }
}

// ---------------- launch ----------------
extern "C" void kernel_launch(void* const* d_in, const int* in_sizes, int n_in,
                              void* d_out, int out_size)
{
    (void)in_sizes; (void)n_in; (void)out_size;
    const float* x     = (const float*)d_in[0];
    const float* g0    = (const float*)d_in[1];
    const float* g1    = (const float*)d_in[2];
    const float* g2    = (const float*)d_in[3];
    const float* alpha = (const float*)d_in[4];
    const float* scale = (const float*)d_in[5];
    const float* bias  = (const float*)d_in[6];
    const int*   perm  = (const int*)d_in[7];
    float* out = (float*)d_out;

    reduce_gates_kernel<<<NPAIRS_TOTAL, 256>>>(g0, g1, g2);
    gather_kernel<<<BATCH, 256>>>(x, perm);
    layer_kernel<0, false><<<dim3(256, 8), 256>>>(0,   nullptr, nullptr, nullptr, nullptr);
    layer_kernel<1, false><<<dim3(255, 8), 256>>>(256, nullptr, nullptr, nullptr, nullptr);
    layer_kernel<0, true ><<<dim3(256, 8), 256>>>(511, alpha, scale, bias, out);
}

// round 2
// speedup vs baseline: 1.1672x; 1.1672x over previous
#include <cuda_runtime.h>

#define BATCH    4096
#define IN_FEAT  4096
#define NPAIRS_TOTAL 767   // 256 + 255 + 256

typedef unsigned long long ull;

// ---------------- scratch (device globals; no allocation allowed) ----------------
__device__ float g_h[(size_t)BATCH * IN_FEAT];        // 64 MB intermediate h
__device__ float g_gred[(size_t)NPAIRS_TOTAL * 1024]; // per (layer,pair): G1[512] | G2[512]

// ---------------- packed f32x2 helpers ----------------
__device__ __forceinline__ ull pack2(float c) {
    ull r; asm("mov.b64 %0, {%1, %1};" : "=l"(r) : "f"(c)); return r;
}
__device__ __forceinline__ void fma2(ull& d, ull a, ull b) {
    asm("fma.rn.f32x2 %0, %1, %2, %3;" : "=l"(d) : "l"(a), "l"(b), "l"(d));
}
__device__ __forceinline__ float2 unpack2(ull v) {
    float2 f; asm("mov.b64 {%0, %1}, %2;" : "=f"(f.x), "=f"(f.y) : "l"(v)); return f;
}

// ---------------- Prep kernel: gate reduction + permuted gather, one launch ----------------
// Blocks [0, 767):      reduce gates for one pair
// Blocks [767, 767+4096): gather one batch row  h[b,q] = x[b, perm[q]]
__global__ __launch_bounds__(256) void prep_kernel(
    const float* __restrict__ g0, const float* __restrict__ g1, const float* __restrict__ g2,
    const float* __restrict__ x,  const int* __restrict__ perm)
{
    __shared__ float sG[4096];
    int tid = threadIdx.x;

    if (blockIdx.x >= NPAIRS_TOTAL) {
        // ---- gather branch: one block per batch row ----
        int b = blockIdx.x - NPAIRS_TOTAL;
        const float* xr = x + (size_t)b * IN_FEAT;
        float* hr = g_h + (size_t)b * IN_FEAT;
#pragma unroll
        for (int c = 0; c < 16; c++) {
            int q = c * 256 + tid;
            hr[q] = xr[perm[q]];
        }
        return;
    }

    // ---- gate-reduce branch ----
    int gb = blockIdx.x;
    const float* src;
    if (gb < 256)      src = g0 + (size_t)gb * 65536;          // 16*4096 floats per pair
    else if (gb < 511) src = g1 + (size_t)(gb - 256) * 65536;
    else               src = g2 + (size_t)(gb - 511) * 65536;

    float acc[16];
#pragma unroll
    for (int t = 0; t < 16; t++) acc[t] = 0.f;
#pragma unroll
    for (int rc = 0; rc < 16; rc++) {
        const float* p = src + rc * 4096;
#pragma unroll
        for (int t = 0; t < 16; t++) acc[t] += p[t * 256 + tid];
    }
#pragma unroll
    for (int t = 0; t < 16; t++) sG[t * 256 + tid] = acc[t];
    __syncthreads();

    float* dst = g_gred + (size_t)gb * 1024;
#pragma unroll
    for (int u = 0; u < 2; u++) {
        int o = u * 256 + tid;          // 0..511
        float s1 = 0.f;
#pragma unroll
        for (int n = 0; n < 8; n++) s1 += sG[o * 8 + n];
        dst[o] = s1;                     // G1[ij][m]
        int ij = o >> 3, nn = o & 7;
        float s2 = 0.f;
#pragma unroll
        for (int m = 0; m < 8; m++) s2 += sG[ij * 64 + m * 8 + nn];
        dst[512 + o] = s2;               // G2[ij][n]
    }
}

// ---------------- Layer kernel ----------------
// grid = (P, 8). 128-thread blocks; each thread processes R=4 batch rows for
// one pair k. Gates staged in SMEM (4KB), broadcast-read; 4 LDS.128 per (i,j)
// now feed 32 FFMA2 (R=4) instead of 16 (R=2) -> halves L1 pressure per flop.
#define RPT 4
template<int OFFSET, bool EPI>
__global__ __launch_bounds__(128) void layer_kernel(
    int gate_base,
    const float* __restrict__ alphap,
    const float* __restrict__ scale,
    const float* __restrict__ bias,
    float* __restrict__ out)
{
    __shared__ float sg[1024];
    int k = blockIdx.x;
    {
        const float4* gsrc = (const float4*)(g_gred + ((size_t)(gate_base + k)) * 1024);
        ((float4*)sg)[threadIdx.x]       = gsrc[threadIdx.x];
        ((float4*)sg)[threadIdx.x + 128] = gsrc[threadIdx.x + 128];
    }
    __syncthreads();

    const size_t col = ((size_t)(OFFSET + 2 * k)) * 8;   // 16 contiguous floats
    const int r0 = blockIdx.y * (128 * RPT) + threadIdx.x;

    float x1[RPT][8], x2[RPT][8];
#pragma unroll
    for (int rr = 0; rr < RPT; rr++) {
        const float4* hp = (const float4*)(g_h + (size_t)(r0 + rr * 128) * IN_FEAT + col);
        float4 a0 = hp[0], a1 = hp[1], b0 = hp[2], b1 = hp[3];
        x1[rr][0]=a0.x; x1[rr][1]=a0.y; x1[rr][2]=a0.z; x1[rr][3]=a0.w;
        x1[rr][4]=a1.x; x1[rr][5]=a1.y; x1[rr][6]=a1.z; x1[rr][7]=a1.w;
        x2[rr][0]=b0.x; x2[rr][1]=b0.y; x2[rr][2]=b0.z; x2[rr][3]=b0.w;
        x2[rr][4]=b1.x; x2[rr][5]=b1.y; x2[rr][6]=b1.z; x2[rr][7]=b1.w;
    }

    ull acc1[RPT][4], acc2[RPT][4];
#pragma unroll
    for (int rr = 0; rr < RPT; rr++)
#pragma unroll
        for (int t = 0; t < 4; t++) { acc1[rr][t] = 0ull; acc2[rr][t] = 0ull; }

    const ulonglong2* sgv = (const ulonglong2*)sg;   // 16B = 2 packed f32x2
#pragma unroll
    for (int i = 0; i < 8; i++) {
#pragma unroll
        for (int j = 0; j < 8; j++) {
            int ij = i * 8 + j;
            ulonglong2 p = sgv[ij * 2];            // G1[ij][0..3]
            ulonglong2 q = sgv[ij * 2 + 1];        // G1[ij][4..7]
            ulonglong2 r = sgv[128 + ij * 2];      // G2[ij][0..3]
            ulonglong2 s = sgv[128 + ij * 2 + 1];  // G2[ij][4..7]
#pragma unroll
            for (int rr = 0; rr < RPT; rr++) {
                ull cd = pack2(x1[rr][i] * x2[rr][j]);
                fma2(acc1[rr][0], cd, p.x); fma2(acc1[rr][1], cd, p.y);
                fma2(acc1[rr][2], cd, q.x); fma2(acc1[rr][3], cd, q.y);
                fma2(acc2[rr][0], cd, r.x); fma2(acc2[rr][1], cd, r.y);
                fma2(acc2[rr][2], cd, s.x); fma2(acc2[rr][3], cd, s.y);
            }
        }
    }

    float al = 1.f;
    float sc[16], bi[16];
    if (EPI) {
        al = __ldg(alphap);
#pragma unroll
        for (int t = 0; t < 16; t++) { sc[t] = __ldg(scale + col + t); bi[t] = __ldg(bias + col + t); }
    }

#pragma unroll
    for (int rr = 0; rr < RPT; rr++) {
        float y[16];
#pragma unroll
        for (int t = 0; t < 4; t++) {
            float2 f1 = unpack2(acc1[rr][t]); y[2 * t]     = f1.x; y[2 * t + 1]     = f1.y;
            float2 f2 = unpack2(acc2[rr][t]); y[8 + 2 * t] = f2.x; y[8 + 2 * t + 1] = f2.y;
        }
        size_t base = (size_t)(r0 + rr * 128) * IN_FEAT + col;
        if (!EPI) {
            float4* hp = (float4*)(g_h + base);
            hp[0] = make_float4(y[0], y[1], y[2], y[3]);
            hp[1] = make_float4(y[4], y[5], y[6], y[7]);
            hp[2] = make_float4(y[8], y[9], y[10], y[11]);
            hp[3] = make_float4(y[12], y[13], y[14], y[15]);
        } else {
#pragma unroll
            for (int t = 0; t < 16; t++) y[t] = al * y[t] * sc[t] + bi[t];
            float4* op = (float4*)(out + base);
            op[0] = make_float4(y[0], y[1], y[2], y[3]);
            op[1] = make_float4(y[4], y[5], y[6], y[7]);
            op[2] = make_float4(y[8], y[9], y[10], y[11]);
            op[3] = make_float4(y[12], y[13], y[14], y[15]);
        }
    }
}

// ---------------- launch ----------------
extern "C" void kernel_launch(void* const* d_in, const int* in_sizes, int n_in,
                              void* d_out, int out_size)
{
    (void)in_sizes; (void)n_in; (void)out_size;
    const float* x     = (const float*)d_in[0];
    const float* g0    = (const float*)d_in[1];
    const float* g1    = (const float*)d_in[2];
    const float* g2    = (const float*)d_in[3];
    const float* alpha = (const float*)d_in[4];
    const float* scale = (const float*)d_in[5];
    const float* bias  = (const float*)d_in[6];
    const int*   perm  = (const int*)d_in[7];
    float* out = (float*)d_out;

    prep_kernel<<<NPAIRS_TOTAL + BATCH, 256>>>(g0, g1, g2, x, perm);
    layer_kernel<0, false><<<dim3(256, 8), 128>>>(0,   nullptr, nullptr, nullptr, nullptr);
    layer_kernel<1, false><<<dim3(255, 8), 128>>>(256, nullptr, nullptr, nullptr, nullptr);
    layer_kernel<0, true ><<<dim3(256, 8), 128>>>(511, alpha, scale, bias, out);
}